// round 4
// baseline (speedup 1.0000x reference)
#include <cuda_runtime.h>

#define RR 8
#define BB 8
#define LL 2048
#define PP 16384
#define HQ 32
#define HKV 8
#define GG 4
#define DD 128
#define NSPLIT 16
#define CHUNK (LL / NSPLIT)   // 128
#define TILE 64
#define RS (RR * NSPLIT)      // 128 partials per (b, hq)
#define SCALE_F 0.08838834764831845f
#define NEGINF -1.0e30f
#define HD (HKV * DD)         // 1024 floats per page row

// Scratch for split-KV partials (device globals; no runtime allocation).
__device__ float g_po[RS * BB * HQ * DD];   // normalized partial O (~16.8MB)
__device__ float g_plse[RS * BB * HQ];      // partial LSE

__global__ void __launch_bounds__(128)
decode_kernel(const float* __restrict__ q,
              const float* __restrict__ kc,
              const float* __restrict__ vc,
              const int* __restrict__ lens,
              const int* __restrict__ bt)
{
    const int split = blockIdx.x;
    const int hkv   = blockIdx.y;
    const int rb    = blockIdx.z;          // r*BB + b
    const int r     = rb >> 3;
    const int b     = rb & 7;
    const int tid   = threadIdx.x;
    const int wid   = tid >> 5;            // 0..3  (warp == head for softmax)
    const int lane  = tid & 31;
    const int half  = lane >> 4;           // half-warp -> token
    const int hl    = lane & 15;           // lane within half

    const int kv_len = lens[rb];
    const int start  = split * CHUNK;
    const int end    = min(start + CHUNK, kv_len);
    const int pbase  = ((r * NSPLIT + split) * BB + b) * HQ + hkv * GG;

    if (end <= start) {
        // Empty split: only mark the LSE; combine skips these entirely.
        if (tid < GG)
            g_plse[pbase + tid] = NEGINF;
        return;
    }

    __shared__ float4 s_s[TILE];      // scores [token][4 heads]
    __shared__ float4 p_s[TILE];      // probs  [token][4 heads]
    __shared__ int    pg_s[2][TILE];  // page per token (double-buffered)
    __shared__ float  sc_s[GG];       // per-head rescale for this tile
    __shared__ float  m_fin[GG], l_fin[GG];

    // Q into registers: head g, dims hl*8 .. hl*8+7
    const float* qb = q + (b * HQ + hkv * GG) * DD + hl * 8;
    float4 q0[GG], q1[GG];
    #pragma unroll
    for (int g = 0; g < GG; ++g) {
        q0[g] = *(const float4*)(qb + g * DD);
        q1[g] = *(const float4*)(qb + g * DD + 4);
    }

    const int*   btb = bt + rb * LL;
    const float* kh  = kc + (long)r * PP * HD + hkv * DD;
    const float* vh  = vc + (long)r * PP * HD + hkv * DD + tid;

    float acc0 = 0.f, acc1 = 0.f, acc2 = 0.f, acc3 = 0.f;
    float m_run = NEGINF, l_run = 0.f;   // warp-uniform state for head `wid`

    int buf = 0;
    for (int tb = start; tb < end; tb += TILE, buf ^= 1) {
        const int nt = min(TILE, end - tb);

        // ---- Page prefetch: lane hl (<8) holds the page for pass hl of its
        //      half-warp. One batched LDG volley -> all 8 pages in flight.
        int page_pre = 0;
        if (hl < 8) {
            const int tt_p = hl * 8 + wid * 2 + half;
            if (tt_p < nt) page_pre = __ldg(btb + tb + tt_p);
        }

        // ---- Phase A, software-pipelined one pass ahead: the current pass's
        //      32 FFMA + 16 SHFL cover the next pass's K load latency.
        int    pg_cur = __shfl_sync(0xffffffffu, page_pre, (lane & 16));
        const float* kt0 = kh + (long)pg_cur * HD + hl * 8;
        float4 k0c = __ldcs((const float4*)kt0);
        float4 k1c = __ldcs((const float4*)(kt0 + 4));

        #pragma unroll
        for (int pass = 0; pass < 8; ++pass) {
            int    pg_nxt = 0;
            float4 k0n = make_float4(0.f, 0.f, 0.f, 0.f);
            float4 k1n = make_float4(0.f, 0.f, 0.f, 0.f);
            if (pass < 7) {
                pg_nxt = __shfl_sync(0xffffffffu, page_pre, (lane & 16) | (pass + 1));
                const float* ktn = kh + (long)pg_nxt * HD + hl * 8;
                k0n = __ldcs((const float4*)ktn);
                k1n = __ldcs((const float4*)(ktn + 4));
            }

            float s0 = q0[0].x*k0c.x + q0[0].y*k0c.y + q0[0].z*k0c.z + q0[0].w*k0c.w
                     + q1[0].x*k1c.x + q1[0].y*k1c.y + q1[0].z*k1c.z + q1[0].w*k1c.w;
            float s1 = q0[1].x*k0c.x + q0[1].y*k0c.y + q0[1].z*k0c.z + q0[1].w*k0c.w
                     + q1[1].x*k1c.x + q1[1].y*k1c.y + q1[1].z*k1c.z + q1[1].w*k1c.w;
            float s2 = q0[2].x*k0c.x + q0[2].y*k0c.y + q0[2].z*k0c.z + q0[2].w*k0c.w
                     + q1[2].x*k1c.x + q1[2].y*k1c.y + q1[2].z*k1c.z + q1[2].w*k1c.w;
            float s3 = q0[3].x*k0c.x + q0[3].y*k0c.y + q0[3].z*k0c.z + q0[3].w*k0c.w
                     + q1[3].x*k1c.x + q1[3].y*k1c.y + q1[3].z*k1c.z + q1[3].w*k1c.w;

            #pragma unroll
            for (int off = 8; off; off >>= 1) {
                s0 += __shfl_xor_sync(0xffffffffu, s0, off);
                s1 += __shfl_xor_sync(0xffffffffu, s1, off);
                s2 += __shfl_xor_sync(0xffffffffu, s2, off);
                s3 += __shfl_xor_sync(0xffffffffu, s3, off);
            }
            const int tt = pass * 8 + wid * 2 + half;
            if (hl == 0) {
                s_s[tt] = (tt < nt) ? make_float4(s0 * SCALE_F, s1 * SCALE_F,
                                                  s2 * SCALE_F, s3 * SCALE_F)
                                    : make_float4(NEGINF, NEGINF, NEGINF, NEGINF);
                pg_s[buf][tt] = pg_cur;
            }
            k0c = k0n; k1c = k1n; pg_cur = pg_nxt;
        }
        __syncthreads();   // sync1: s_s / pg_s[buf] ready

        // ---- Online softmax: warp `wid` owns head `wid`, fully warp-local.
        {
            const float* sf = (const float*)s_s;
            const float  xa = sf[lane * 4 + wid];
            const float  xb = sf[(lane + 32) * 4 + wid];
            float x = fmaxf(xa, xb);
            #pragma unroll
            for (int off = 16; off; off >>= 1)
                x = fmaxf(x, __shfl_xor_sync(0xffffffffu, x, off));
            const float mo = m_run;
            const float mn = fmaxf(mo, x);
            const float scl = __expf(mo - mn);
            m_run = mn;
            if (lane == 0) sc_s[wid] = scl;
            const float pa = __expf(xa - mn);
            const float pb = __expf(xb - mn);
            float* pf = (float*)p_s;
            pf[lane * 4 + wid]        = pa;
            pf[(lane + 32) * 4 + wid] = pb;
            float ps = pa + pb;
            #pragma unroll
            for (int off = 16; off; off >>= 1)
                ps += __shfl_xor_sync(0xffffffffu, ps, off);
            l_run = l_run * scl + ps;
        }
        __syncthreads();   // sync2: p_s / sc_s ready

        // ---- Rescale + Phase B: thread tid owns dim d = tid for all 4 heads.
        const float c0 = sc_s[0], c1 = sc_s[1], c2 = sc_s[2], c3 = sc_s[3];
        acc0 *= c0; acc1 *= c1; acc2 *= c2; acc3 *= c3;

        #pragma unroll 16
        for (int j = 0; j < nt; ++j) {
            const float4 p4 = p_s[j];
            const float  v  = __ldcs(vh + (long)pg_s[buf][j] * HD);
            acc0 += p4.x * v; acc1 += p4.y * v;
            acc2 += p4.z * v; acc3 += p4.w * v;
        }
        // No barrier here: pg double-buffered; p_s/sc_s WAR protected by sync1
        // of the next iteration (writers pass it only after all warps leave B).
    }

    if (lane == 0) { m_fin[wid] = m_run; l_fin[wid] = l_run; }
    __syncthreads();

    const float l0 = fmaxf(l_fin[0], 1e-30f);
    const float l1 = fmaxf(l_fin[1], 1e-30f);
    const float l2 = fmaxf(l_fin[2], 1e-30f);
    const float l3 = fmaxf(l_fin[3], 1e-30f);
    g_po[(pbase + 0) * DD + tid] = acc0 / l0;
    g_po[(pbase + 1) * DD + tid] = acc1 / l1;
    g_po[(pbase + 2) * DD + tid] = acc2 / l2;
    g_po[(pbase + 3) * DD + tid] = acc3 / l3;
    if (tid < GG)
        g_plse[pbase + tid] = m_fin[tid] + __logf(fmaxf(l_fin[tid], 1e-30f));
}

#define CTHREADS 512
#define NSLICE 4
#define PER_SLICE (RS / NSLICE)   // 32

__global__ void __launch_bounds__(CTHREADS)
combine_kernel(float* __restrict__ out)
{
    const int bh  = blockIdx.x;     // b*HQ + hq
    const int tid = threadIdx.x;
    const int d   = tid & 127;      // output dim
    const int sl  = tid >> 7;       // slice 0..3

    __shared__ float lse_s[RS];
    __shared__ float accs[NSLICE][DD];
    __shared__ float wss[NSLICE];

    if (tid < RS)
        lse_s[tid] = g_plse[tid * (BB * HQ) + bh];
    __syncthreads();

    float gm = NEGINF;
    #pragma unroll
    for (int i = 0; i < RS; ++i)
        gm = fmaxf(gm, lse_s[i]);

    // Each slice accumulates its 32 partials; fully unrolled so the
    // (predicated) independent LDGs are front-batched.
    float acc = 0.f, ws = 0.f;
    #pragma unroll
    for (int t = 0; t < PER_SLICE; ++t) {
        const int   i   = sl * PER_SLICE + t;
        const float lse = lse_s[i];
        if (lse > -5.0e29f) {
            const float w = __expf(lse - gm);
            ws  += w;
            acc += w * __ldg(&g_po[(i * (BB * HQ) + bh) * DD + d]);
        }
    }
    accs[sl][d] = acc;
    if (d == 0) wss[sl] = ws;
    __syncthreads();

    if (sl == 0) {
        const float a  = accs[0][d] + accs[1][d] + accs[2][d] + accs[3][d];
        const float wt = wss[0] + wss[1] + wss[2] + wss[3];
        out[bh * DD + d] = a / fmaxf(wt, 1e-30f);
    }
}

extern "C" void kernel_launch(void* const* d_in, const int* in_sizes, int n_in,
                              void* d_out, int out_size)
{
    (void)in_sizes; (void)n_in; (void)out_size;
    const float* q    = (const float*)d_in[0];
    const float* kc   = (const float*)d_in[1];
    const float* vc   = (const float*)d_in[2];
    const int*   lens = (const int*)d_in[3];
    const int*   bt   = (const int*)d_in[4];

    dim3 grid1(NSPLIT, HKV, RR * BB);
    decode_kernel<<<grid1, 128>>>(q, kc, vc, lens, bt);
    combine_kernel<<<BB * HQ, CTHREADS>>>((float*)d_out);
}

// round 5
// speedup vs baseline: 1.1928x; 1.1928x over previous
#include <cuda_runtime.h>

#define RR 8
#define BB 8
#define LL 2048
#define PP 16384
#define HQ 32
#define HKV 8
#define GG 4
#define DD 128
#define NSPLIT 16
#define CHUNK (LL / NSPLIT)   // 128
#define TILE 64
#define RS (RR * NSPLIT)      // 128 partials per (b, hq)
#define SCALE_F 0.08838834764831845f
#define NEGINF -1.0e30f
#define HD (HKV * DD)         // 1024 floats per page row

// Scratch for split-KV partials (device globals; no runtime allocation).
__device__ float g_po[RS * BB * HQ * DD];   // normalized partial O (~16.8MB)
__device__ float g_plse[RS * BB * HQ];      // partial LSE

__global__ void __launch_bounds__(128)
decode_kernel(const float* __restrict__ q,
              const float* __restrict__ kc,
              const float* __restrict__ vc,
              const int* __restrict__ lens,
              const int* __restrict__ bt)
{
    const int split = blockIdx.x;
    const int hkv   = blockIdx.y;
    const int rb    = blockIdx.z;          // r*BB + b
    const int r     = rb >> 3;
    const int b     = rb & 7;
    const int tid   = threadIdx.x;
    const int wid   = tid >> 5;            // 0..3  (warp == head for softmax)
    const int lane  = tid & 31;
    const int half  = lane >> 4;           // half-warp -> token pair
    const int hl    = lane & 15;           // lane within half

    const int kv_len = lens[rb];
    const int start  = split * CHUNK;
    const int end    = min(start + CHUNK, kv_len);
    const int pbase  = ((r * NSPLIT + split) * BB + b) * HQ + hkv * GG;

    if (end <= start) {
        // Empty split: only mark the LSE; combine skips these entirely.
        if (tid < GG)
            g_plse[pbase + tid] = NEGINF;
        return;
    }

    __shared__ float4 s_s[TILE];      // scores [token][4 heads]
    __shared__ float4 p_s[TILE];      // probs  [token][4 heads]
    __shared__ int    pg_s[2][TILE];  // page per token (double-buffered)
    __shared__ float  sc_s[GG];       // per-head rescale for this tile
    __shared__ float  m_fin[GG], l_fin[GG];

    // Q into registers: head g, dims hl*8 .. hl*8+7
    const float* qb = q + (b * HQ + hkv * GG) * DD + hl * 8;
    float4 q0[GG], q1[GG];
    #pragma unroll
    for (int g = 0; g < GG; ++g) {
        q0[g] = *(const float4*)(qb + g * DD);
        q1[g] = *(const float4*)(qb + g * DD + 4);
    }

    const int*   btb = bt + rb * LL;
    const float* kh  = kc + (long)r * PP * HD + hkv * DD;
    const float* vh  = vc + (long)r * PP * HD + hkv * DD + tid;

    float acc0 = 0.f, acc1 = 0.f, acc2 = 0.f, acc3 = 0.f;
    float m_run = NEGINF, l_run = 0.f;   // warp-uniform state for head `wid`

    const int hw = wid * 2 + half;       // half-warp id 0..7

    int buf = 0;
    for (int tb = start; tb < end; tb += TILE, buf ^= 1) {
        const int nt = min(TILE, end - tb);

        // ---- Phase A: scores. Half-warp per 2 tokens, 16 tokens/CTA/pass.
        //      4 independent LDG.128 per thread per pass (MLP=4).
        #pragma unroll
        for (int pass = 0; pass < 4; ++pass) {
            const int  ta = pass * 16 + hw * 2;   // token a
            const int  tc = ta + 1;               // token b
            const bool va = (ta < nt);
            const bool vb = (tc < nt);
            const int  pga = va ? __ldg(btb + tb + ta) : 0;
            const int  pgb = vb ? __ldg(btb + tb + tc) : 0;
            const float* kta = kh + (long)pga * HD + hl * 8;
            const float* ktb = kh + (long)pgb * HD + hl * 8;
            const float4 k0a = __ldcs((const float4*)kta);
            const float4 k1a = __ldcs((const float4*)(kta + 4));
            const float4 k0b = __ldcs((const float4*)ktb);
            const float4 k1b = __ldcs((const float4*)(ktb + 4));

            float s0a = q0[0].x*k0a.x + q0[0].y*k0a.y + q0[0].z*k0a.z + q0[0].w*k0a.w
                      + q1[0].x*k1a.x + q1[0].y*k1a.y + q1[0].z*k1a.z + q1[0].w*k1a.w;
            float s1a = q0[1].x*k0a.x + q0[1].y*k0a.y + q0[1].z*k0a.z + q0[1].w*k0a.w
                      + q1[1].x*k1a.x + q1[1].y*k1a.y + q1[1].z*k1a.z + q1[1].w*k1a.w;
            float s2a = q0[2].x*k0a.x + q0[2].y*k0a.y + q0[2].z*k0a.z + q0[2].w*k0a.w
                      + q1[2].x*k1a.x + q1[2].y*k1a.y + q1[2].z*k1a.z + q1[2].w*k1a.w;
            float s3a = q0[3].x*k0a.x + q0[3].y*k0a.y + q0[3].z*k0a.z + q0[3].w*k0a.w
                      + q1[3].x*k1a.x + q1[3].y*k1a.y + q1[3].z*k1a.z + q1[3].w*k1a.w;

            float s0b = q0[0].x*k0b.x + q0[0].y*k0b.y + q0[0].z*k0b.z + q0[0].w*k0b.w
                      + q1[0].x*k1b.x + q1[0].y*k1b.y + q1[0].z*k1b.z + q1[0].w*k1b.w;
            float s1b = q0[1].x*k0b.x + q0[1].y*k0b.y + q0[1].z*k0b.z + q0[1].w*k0b.w
                      + q1[1].x*k1b.x + q1[1].y*k1b.y + q1[1].z*k1b.z + q1[1].w*k1b.w;
            float s2b = q0[2].x*k0b.x + q0[2].y*k0b.y + q0[2].z*k0b.z + q0[2].w*k0b.w
                      + q1[2].x*k1b.x + q1[2].y*k1b.y + q1[2].z*k1b.z + q1[2].w*k1b.w;
            float s3b = q0[3].x*k0b.x + q0[3].y*k0b.y + q0[3].z*k0b.z + q0[3].w*k0b.w
                      + q1[3].x*k1b.x + q1[3].y*k1b.y + q1[3].z*k1b.z + q1[3].w*k1b.w;

            #pragma unroll
            for (int off = 8; off; off >>= 1) {
                s0a += __shfl_xor_sync(0xffffffffu, s0a, off);
                s1a += __shfl_xor_sync(0xffffffffu, s1a, off);
                s2a += __shfl_xor_sync(0xffffffffu, s2a, off);
                s3a += __shfl_xor_sync(0xffffffffu, s3a, off);
                s0b += __shfl_xor_sync(0xffffffffu, s0b, off);
                s1b += __shfl_xor_sync(0xffffffffu, s1b, off);
                s2b += __shfl_xor_sync(0xffffffffu, s2b, off);
                s3b += __shfl_xor_sync(0xffffffffu, s3b, off);
            }
            if (hl == 0) {
                s_s[ta] = va ? make_float4(s0a * SCALE_F, s1a * SCALE_F,
                                           s2a * SCALE_F, s3a * SCALE_F)
                             : make_float4(NEGINF, NEGINF, NEGINF, NEGINF);
                s_s[tc] = vb ? make_float4(s0b * SCALE_F, s1b * SCALE_F,
                                           s2b * SCALE_F, s3b * SCALE_F)
                             : make_float4(NEGINF, NEGINF, NEGINF, NEGINF);
                pg_s[buf][ta] = pga;
                pg_s[buf][tc] = pgb;
            }
        }
        __syncthreads();   // sync1: s_s / pg_s[buf] ready

        // ---- Online softmax: warp `wid` owns head `wid`, fully warp-local.
        {
            const float* sf = (const float*)s_s;
            const float  xa = sf[lane * 4 + wid];
            const float  xb = sf[(lane + 32) * 4 + wid];
            float x = fmaxf(xa, xb);
            #pragma unroll
            for (int off = 16; off; off >>= 1)
                x = fmaxf(x, __shfl_xor_sync(0xffffffffu, x, off));
            const float mo = m_run;
            const float mn = fmaxf(mo, x);
            const float scl = __expf(mo - mn);
            m_run = mn;
            if (lane == 0) sc_s[wid] = scl;
            const float pa = __expf(xa - mn);
            const float pb = __expf(xb - mn);
            float* pf = (float*)p_s;
            pf[lane * 4 + wid]        = pa;
            pf[(lane + 32) * 4 + wid] = pb;
            float ps = pa + pb;
            #pragma unroll
            for (int off = 16; off; off >>= 1)
                ps += __shfl_xor_sync(0xffffffffu, ps, off);
            l_run = l_run * scl + ps;
        }
        __syncthreads();   // sync2: p_s / sc_s ready

        // ---- Rescale + Phase B: thread tid owns dim d = tid for all 4 heads.
        const float c0 = sc_s[0], c1 = sc_s[1], c2 = sc_s[2], c3 = sc_s[3];
        acc0 *= c0; acc1 *= c1; acc2 *= c2; acc3 *= c3;

        #pragma unroll 8
        for (int j = 0; j < nt; ++j) {
            const float4 p4 = p_s[j];
            const float  v  = __ldcs(vh + (long)pg_s[buf][j] * HD);
            acc0 += p4.x * v; acc1 += p4.y * v;
            acc2 += p4.z * v; acc3 += p4.w * v;
        }
        // No barrier here: pg double-buffered; p_s/sc_s WAR protected by sync1
        // of the next iteration (writers pass it only after all warps leave B).
    }

    if (lane == 0) { m_fin[wid] = m_run; l_fin[wid] = l_run; }
    __syncthreads();

    const float l0 = fmaxf(l_fin[0], 1e-30f);
    const float l1 = fmaxf(l_fin[1], 1e-30f);
    const float l2 = fmaxf(l_fin[2], 1e-30f);
    const float l3 = fmaxf(l_fin[3], 1e-30f);
    g_po[(pbase + 0) * DD + tid] = acc0 / l0;
    g_po[(pbase + 1) * DD + tid] = acc1 / l1;
    g_po[(pbase + 2) * DD + tid] = acc2 / l2;
    g_po[(pbase + 3) * DD + tid] = acc3 / l3;
    if (tid < GG)
        g_plse[pbase + tid] = m_fin[tid] + __logf(fmaxf(l_fin[tid], 1e-30f));
}

#define CTHREADS 512
#define NSLICE 4
#define PER_SLICE (RS / NSLICE)   // 32

__global__ void __launch_bounds__(CTHREADS)
combine_kernel(float* __restrict__ out)
{
    const int bh  = blockIdx.x;     // b*HQ + hq
    const int tid = threadIdx.x;
    const int d   = tid & 127;      // output dim
    const int sl  = tid >> 7;       // slice 0..3

    __shared__ float lse_s[RS];
    __shared__ float accs[NSLICE][DD];
    __shared__ float wss[NSLICE];

    if (tid < RS)
        lse_s[tid] = g_plse[tid * (BB * HQ) + bh];
    __syncthreads();

    float gm = NEGINF;
    #pragma unroll
    for (int i = 0; i < RS; ++i)
        gm = fmaxf(gm, lse_s[i]);

    // Each slice accumulates its 32 partials; fully unrolled so the
    // (predicated) independent LDGs are front-batched.
    float acc = 0.f, ws = 0.f;
    #pragma unroll
    for (int t = 0; t < PER_SLICE; ++t) {
        const int   i   = sl * PER_SLICE + t;
        const float lse = lse_s[i];
        if (lse > -5.0e29f) {
            const float w = __expf(lse - gm);
            ws  += w;
            acc += w * __ldg(&g_po[(i * (BB * HQ) + bh) * DD + d]);
        }
    }
    accs[sl][d] = acc;
    if (d == 0) wss[sl] = ws;
    __syncthreads();

    if (sl == 0) {
        const float a  = accs[0][d] + accs[1][d] + accs[2][d] + accs[3][d];
        const float wt = wss[0] + wss[1] + wss[2] + wss[3];
        out[bh * DD + d] = a / fmaxf(wt, 1e-30f);
    }
}

extern "C" void kernel_launch(void* const* d_in, const int* in_sizes, int n_in,
                              void* d_out, int out_size)
{
    (void)in_sizes; (void)n_in; (void)out_size;
    const float* q    = (const float*)d_in[0];
    const float* kc   = (const float*)d_in[1];
    const float* vc   = (const float*)d_in[2];
    const int*   lens = (const int*)d_in[3];
    const int*   bt   = (const int*)d_in[4];

    dim3 grid1(NSPLIT, HKV, RR * BB);
    decode_kernel<<<grid1, 128>>>(q, kc, vc, lens, bt);
    combine_kernel<<<BB * HQ, CTHREADS>>>((float*)d_out);
}